// round 16
// baseline (speedup 1.0000x reference)
#include <cuda_runtime.h>
#include <cuda_fp16.h>
#include <cstdint>

#define NTOK 8192
#define HCH  2048
#define DH   128

// ---------------- device scratch ----------------
__device__ __align__(16) __half g_xh[NTOK * HCH];
__device__ __align__(16) __half g_wh[384 * HCH];
__device__ __align__(16) __half g_qh[NTOK * DH];   // scale folded
__device__ __align__(16) __half g_kh[NTOK * DH];
__device__ __align__(16) __half g_vh[NTOK * DH];
__device__ __align__(16) float  g_O[2][NTOK * DH]; // unnormalized per split
__device__ float g_l[2][NTOK];
__device__ __align__(16) uint32_t g_maskb[(size_t)NTOK * NTOK / 32];  // 8MB bitmask
__device__ int g_mask4;

#define NMWORDS (NTOK * NTOK / 32)   // 2097152 output u32 words

// ---------------- helpers ----------------
__device__ __forceinline__ uint32_t smem_u32(const void* p) {
  uint32_t a;
  asm("{ .reg .u64 t; cvta.to.shared.u64 t, %1; cvt.u32.u64 %0, t; }" : "=r"(a) : "l"(p));
  return a;
}
__device__ __forceinline__ void ldm_x4(uint32_t* r, uint32_t a) {
  asm volatile("ldmatrix.sync.aligned.m8n8.x4.shared.b16 {%0,%1,%2,%3}, [%4];"
    : "=r"(r[0]), "=r"(r[1]), "=r"(r[2]), "=r"(r[3]) : "r"(a));
}
__device__ __forceinline__ void ldm_x4t(uint32_t* r, uint32_t a) {
  asm volatile("ldmatrix.sync.aligned.m8n8.x4.trans.shared.b16 {%0,%1,%2,%3}, [%4];"
    : "=r"(r[0]), "=r"(r[1]), "=r"(r[2]), "=r"(r[3]) : "r"(a));
}
__device__ __forceinline__ void stm_x4(uint32_t a, uint32_t r0, uint32_t r1,
                                       uint32_t r2, uint32_t r3) {
  asm volatile("stmatrix.sync.aligned.m8n8.x4.shared.b16 [%0], {%1,%2,%3,%4};"
    :: "r"(a), "r"(r0), "r"(r1), "r"(r2), "r"(r3) : "memory");
}
__device__ __forceinline__ void mma16816(float* d, const uint32_t* a, const uint32_t* b) {
  asm volatile("mma.sync.aligned.m16n8k16.row.col.f32.f16.f16.f32 "
    "{%0,%1,%2,%3}, {%4,%5,%6,%7}, {%8,%9}, {%0,%1,%2,%3};"
    : "+f"(d[0]), "+f"(d[1]), "+f"(d[2]), "+f"(d[3])
    : "r"(a[0]), "r"(a[1]), "r"(a[2]), "r"(a[3]), "r"(b[0]), "r"(b[1]));
}
__device__ __forceinline__ void cp16(uint32_t dst, const void* src) {
  asm volatile("cp.async.cg.shared.global [%0], [%1], 16;" :: "r"(dst), "l"(src) : "memory");
}
#define CP_COMMIT() asm volatile("cp.async.commit_group;" ::: "memory")
#define CP_WAIT0()  asm volatile("cp.async.wait_group 0;" ::: "memory")
#define CP_WAIT1()  asm volatile("cp.async.wait_group 1;" ::: "memory")
__device__ __forceinline__ __half2 hexp2_(__half2 x) {
  uint32_t r, a = *(uint32_t*)&x;
  asm("ex2.approx.f16x2 %0, %1;" : "=r"(r) : "r"(a));
  return *(__half2*)&r;
}
__device__ __forceinline__ uint32_t pack_h2(float x, float y) {
  __half2 h = __floats2half2_rn(x, y);
  return *(uint32_t*)&h;
}

// ---------------- mask dtype detect (1 block) ----------------
__global__ void detect_kernel(const unsigned* __restrict__ m) {
  __shared__ int s_ok;
  if (threadIdx.x == 0) s_ok = 1;
  __syncthreads();
  unsigned w = m[threadIdx.x];          // 64 threads, first 64 words
  if (w > 1u && w != 0x3f800000u) s_ok = 0;
  __syncthreads();
  if (threadIdx.x == 0) g_mask4 = s_ok;
}

// ---------------- fp32 -> fp16 (x and W fused) ----------------
#define NX4 (NTOK * HCH / 4)
#define NW4 (384 * HCH / 4)
__global__ __launch_bounds__(256) void cvt_kernel(const float* __restrict__ x,
                                                  const float* __restrict__ w) {
  int i = blockIdx.x * 256 + threadIdx.x;
  const float* src;
  __half* dst;
  int j;
  if (i < NX4) { src = x; dst = g_xh; j = i; }
  else         { src = w; dst = g_wh; j = i - NX4; }
  float4 v = ((const float4*)src)[j];
  uint2 o; o.x = pack_h2(v.x, v.y); o.y = pack_h2(v.z, v.w);
  ((uint2*)dst)[j] = o;
}

// ---------------- QKV GEMM + in-loop mask bit-packing ----------------
// GEMM: BM=64, BN=128, BK=64, 3-stage cp.async; grid (128, 3); smem 72KB.
// Mask: each warp converts 24 u32 bitmask words per iteration (loads issued
// before the MMA block, ballots+stores after) — 256MB DRAM hidden under HMMA.
__global__ __launch_bounds__(256) void qkv_kernel(const void* __restrict__ mask) {
  extern __shared__ __align__(16) char smem[];
  const uint32_t sb = smem_u32(smem);
  const int tid = threadIdx.x, lane = tid & 31, wid = tid >> 5;
  const int wr = wid & 3, wc = wid >> 2;
  const int g = lane >> 2, c4 = lane & 3;
  const int m0 = blockIdx.x * 64;
  const int which = blockIdx.y;
  const __half* wsrc = g_wh + (size_t)which * 128 * HCH;
  const uint32_t gw = ((uint32_t)blockIdx.y * 128 + blockIdx.x) * 8 + wid;
  const int is4 = g_mask4;
  const unsigned* m4 = (const unsigned*)mask;
  const uint8_t* m8 = (const uint8_t*)mask;

  float acc[8][4];
#pragma unroll
  for (int nt = 0; nt < 8; nt++)
#pragma unroll
    for (int r = 0; r < 4; r++) acc[nt][r] = 0.f;

  const int x7 = lane & 7, hiA = lane >> 4, hiB = (lane >> 3) & 1, q2 = (lane >> 4) & 1;
  const int l15 = lane & 15;

  auto issue = [&](int kc) {
    int st = kc % 3;
    uint32_t bufA = sb + (uint32_t)st * 8192;
    uint32_t bufB = sb + 24576 + (uint32_t)st * 16384;
#pragma unroll
    for (int i = 0; i < 2; i++) {
      int idx = tid + i * 256;
      int r = idx >> 3, ch = idx & 7;
      uint32_t sw = (uint32_t)r * 128 + (uint32_t)((ch ^ (r & 7)) << 4);
      cp16(bufA + sw, g_xh + (size_t)(m0 + r) * HCH + kc * 64 + ch * 8);
    }
#pragma unroll
    for (int i = 0; i < 4; i++) {
      int idx = tid + i * 256;
      int r = idx >> 3, ch = idx & 7;
      uint32_t sw = (uint32_t)r * 128 + (uint32_t)((ch ^ (r & 7)) << 4);
      cp16(bufB + sw, wsrc + (size_t)r * HCH + kc * 64 + ch * 8);
    }
    CP_COMMIT();
  };

  issue(0);
  issue(1);
  for (int kc = 0; kc < 32; kc++) {
    if (kc < 31) { CP_WAIT1(); } else { CP_WAIT0(); }
    __syncthreads();
    if (kc < 30) issue(kc + 2);

    // ---- mask loads for this iteration's 24 output words (fly under MMA) ----
    const uint32_t wchunk = (gw * 32 + (uint32_t)kc) * 24;
    uint32_t mval[6][4];
#pragma unroll
    for (int gr = 0; gr < 6; gr++) {
      uint32_t wb = wchunk + gr * 4;
      if (wb < (uint32_t)NMWORDS) {
        if (is4) {
#pragma unroll
          for (int r = 0; r < 4; r++)
            mval[gr][r] = m4[(size_t)(wb + r) * 32 + lane];
        } else {
#pragma unroll
          for (int r = 0; r < 4; r++)
            mval[gr][r] = (uint32_t)m8[(size_t)(wb + r) * 32 + lane];
        }
      }
    }

    int st = kc % 3;
    const uint32_t bufA = sb + (uint32_t)st * 8192;
    const uint32_t bufB = sb + 24576 + (uint32_t)st * 16384;
    const uint32_t aBase = bufA + (uint32_t)(wr * 16 + l15) * 128;
    const uint32_t bBase = bufB + (uint32_t)(wc * 64 + x7) * 128;
#pragma unroll
    for (int ks = 0; ks < 4; ks++) {
      uint32_t a0[4];
      ldm_x4(a0, aBase + (((ks * 2 + hiA) ^ x7) << 4));
#pragma unroll
      for (int nt = 0; nt < 8; nt += 2) {
        uint32_t b[4];
        ldm_x4(b, bBase + (uint32_t)(nt + q2) * 8 * 128 + (((ks * 2 + hiB) ^ x7) << 4));
        mma16816(acc[nt], a0, b);
        mma16816(acc[nt + 1], a0, b + 2);
      }
    }

    // ---- ballots + bitmask stores ----
#pragma unroll
    for (int gr = 0; gr < 6; gr++) {
      uint32_t wb = wchunk + gr * 4;
      if (wb < (uint32_t)NMWORDS) {
        uint4 o;
        o.x = __ballot_sync(0xffffffffu, mval[gr][0] != 0u);
        o.y = __ballot_sync(0xffffffffu, mval[gr][1] != 0u);
        o.z = __ballot_sync(0xffffffffu, mval[gr][2] != 0u);
        o.w = __ballot_sync(0xffffffffu, mval[gr][3] != 0u);
        if (lane == 0) *(uint4*)&g_maskb[wb] = o;
      }
    }
  }

  const float sc = (which == 0) ? (1.4426950408889634f / 128.0f) : 1.0f;
  __half* dst = (which == 0) ? g_qh : (which == 1) ? g_kh : g_vh;
#pragma unroll
  for (int h = 0; h < 2; h++) {
    int row = m0 + wr * 16 + g + h * 8;
#pragma unroll
    for (int nt = 0; nt < 8; nt++) {
      int col = wc * 64 + nt * 8 + c4 * 2;
      *(uint32_t*)(dst + (size_t)row * DH + col) =
          pack_h2(acc[nt][h * 2] * sc, acc[nt][h * 2 + 1] * sc);
    }
  }
}

// ---------------- attention (R15 verbatim — bitmask path) ----------------
// grid 128 = 64 q-tiles x 2 kv-splits. BM=BN=128, 8 warps (4x2).
// smem: K 2x32KB, V 2x32KB, P 32KB, maskbits 2x2KB, L 1KB
#define SK 0
#define SV 65536
#define SP 131072
#define SM2 163840
#define SL (SM2 + 4096)
#define A_SMEM (SL + 1024)

__global__ __launch_bounds__(256, 1) void attn_kernel() {
  extern __shared__ __align__(16) char smem[];
  const uint32_t sb = smem_u32(smem);
  const int tid = threadIdx.x, lane = tid & 31, wid = tid >> 5;
  const int wr = wid & 3, wc = wid >> 2;
  const int g = lane >> 2, c4 = lane & 3;
  const int qt = blockIdx.x >> 1;
  const int qbase = qt * 128;
  const int split = blockIdx.x & 1;
  const int barid = wr + 1;

  const int x7 = lane & 7, hiA = lane >> 4, hiB = (lane >> 3) & 1, q2 = (lane >> 4) & 1;
  const int l15 = lane & 15;
  const int c42 = c4 * 2;

  auto issue = [&](int kb) {
    const int kcol = split * 4096 + kb * 128;
    const uint32_t kB = sb + SK + (uint32_t)(kb & 1) * 32768;
    const uint32_t vB = sb + SV + (uint32_t)(kb & 1) * 32768;
    const uint32_t mB = sb + SM2 + (uint32_t)(kb & 1) * 2048;
#pragma unroll
    for (int i = 0; i < 8; i++) {
      int idx = tid + i * 256;
      int r = idx >> 4, ch = idx & 15;
      uint32_t sw = (uint32_t)r * 256 + (uint32_t)((ch ^ (r & 7)) << 4);
      cp16(kB + sw, g_kh + (size_t)(kcol + r) * DH + ch * 8);
      cp16(vB + sw, g_vh + (size_t)(kcol + r) * DH + ch * 8);
    }
    if (tid < 128) {   // mask bits: 16B per row
      cp16(mB + (uint32_t)tid * 16,
           (const uint8_t*)g_maskb + (size_t)(qbase + tid) * 1024 + split * 512 + kb * 16);
    }
    CP_COMMIT();
  };

  issue(0);

  // stage Q into the P region, extract fragments into registers
#pragma unroll
  for (int i = 0; i < 8; i++) {
    int idx = tid + i * 256;
    int r = idx >> 4, ch = idx & 15;
    uint4 v = *(const uint4*)(g_qh + (size_t)(qbase + r) * DH + ch * 8);
    *(uint4*)(smem + SP + r * 256 + ((ch ^ (r & 7)) << 4)) = v;
  }
  __syncthreads();
  uint32_t qa[8][2][4];
  {
    const uint32_t qB = sb + SP + (uint32_t)(wr * 32 + l15) * 256;
#pragma unroll
    for (int ks = 0; ks < 8; ks++) {
      ldm_x4(qa[ks][0], qB + (((ks * 2 + hiA) ^ x7) << 4));
      ldm_x4(qa[ks][1], qB + 16 * 256 + (((ks * 2 + hiA) ^ x7) << 4));
    }
  }
  __syncthreads();   // everyone has Q frags before P overwrites begin

  float o[2][8][4];
#pragma unroll
  for (int mt = 0; mt < 2; mt++)
#pragma unroll
    for (int nt = 0; nt < 8; nt++)
#pragma unroll
      for (int r = 0; r < 4; r++) o[mt][nt][r] = 0.f;
  float lp[2][2] = {{0.f, 0.f}, {0.f, 0.f}};

  const int t8 = lane >> 3;            // stmatrix tile index
  const int hh = t8 & 1, ntp = t8 >> 1, r8 = lane & 7;

  for (int kb = 0; kb < 32; kb++) {
    CP_WAIT0();
    __syncthreads();
    if (kb < 31) issue(kb + 1);

    const uint32_t kB = sb + SK + (uint32_t)(kb & 1) * 32768 + (uint32_t)(wc * 64 + x7) * 256;
    const uint32_t vB = sb + SV + (uint32_t)(kb & 1) * 32768 + (uint32_t)l15 * 256;
    const uint32_t mB = sb + SM2 + (uint32_t)(kb & 1) * 2048 + (uint32_t)(wc * 8);

    // ---- S = Q @ K^T ----
    float s[2][8][4];
#pragma unroll
    for (int mt = 0; mt < 2; mt++)
#pragma unroll
      for (int nt = 0; nt < 8; nt++)
#pragma unroll
        for (int r = 0; r < 4; r++) s[mt][nt][r] = 0.f;
#pragma unroll
    for (int ks = 0; ks < 8; ks++) {
#pragma unroll
      for (int nt = 0; nt < 8; nt += 2) {
        uint32_t b[4];
        ldm_x4(b, kB + (uint32_t)(nt + q2) * 8 * 256 + (((ks * 2 + hiB) ^ x7) << 4));
        mma16816(s[0][nt], qa[ks][0], b);
        mma16816(s[1][nt], qa[ks][1], b);
        mma16816(s[0][nt + 1], qa[ks][0], b + 2);
        mma16816(s[1][nt + 1], qa[ks][1], b + 2);
      }
    }

    // ---- fp16x2 softmax (multiplier from mask bits), stmatrix P ----
    asm volatile("bar.sync %0, 64;" :: "r"(barid) : "memory");
#pragma unroll
    for (int mt = 0; mt < 2; mt++) {
      uint32_t pk[2][8];
#pragma unroll
      for (int h = 0; h < 2; h++) {
        int rowl = wr * 32 + mt * 16 + h * 8 + g;
        uint64_t mb;
        asm volatile("ld.shared.b64 %0, [%1];" : "=l"(mb) : "r"(mB + (uint32_t)rowl * 16));
        uint32_t mlo = (uint32_t)mb, mhi = (uint32_t)(mb >> 32);
        __half2 hs = __halves2half2(__float2half(0.f), __float2half(0.f));
#pragma unroll
        for (int nt = 0; nt < 8; nt++) {
          uint32_t b2 = ((nt < 4) ? (mlo >> (nt * 8 + c42)) : (mhi >> ((nt - 4) * 8 + c42))) & 3u;
          uint32_t m2u = 0x3C003C00u - (b2 & 1u) * 0x3C00u - (b2 >> 1) * 0x3C000000u;
          __half2 m2 = *(__half2*)&m2u;
          __half2 sh = __floats2half2_rn(s[mt][nt][h * 2], s[mt][nt][h * 2 + 1]);
          __half2 p = __hmul2(hexp2_(sh), m2);
          pk[h][nt] = *(uint32_t*)&p;
          hs = __hadd2(hs, p);
        }
        float2 f = __half22float2(hs);
        lp[mt][h] += f.x + f.y;
      }
      int srow = wr * 32 + mt * 16 + hh * 8 + r8;
      uint32_t sbase = sb + SP + (uint32_t)srow * 256;
      int sr7 = srow & 7;
#pragma unroll
      for (int j = 0; j < 4; j++) {
        int ntj = 2 * j + ntp;
        uint32_t addr = sbase + (uint32_t)(((wc * 8 + ntj) ^ sr7) << 4);
        stm_x4(addr, pk[0][2 * j], pk[1][2 * j], pk[0][2 * j + 1], pk[1][2 * j + 1]);
      }
    }
    asm volatile("bar.sync %0, 64;" :: "r"(barid) : "memory");

    // ---- O += P @ V ----
    const uint32_t pB = sb + SP + (uint32_t)(wr * 32 + l15) * 256;
#pragma unroll
    for (int ks = 0; ks < 8; ks++) {
      uint32_t a0[4], a1[4];
      ldm_x4(a0, pB + (((ks * 2 + hiA) ^ x7) << 4));
      ldm_x4(a1, pB + 16 * 256 + (((ks * 2 + hiA) ^ x7) << 4));
      uint32_t vrow = vB + (uint32_t)(ks * 16) * 256;
#pragma unroll
      for (int nt = 0; nt < 8; nt += 2) {
        uint32_t b[4];
        ldm_x4t(b, vrow + (uint32_t)(((wc * 8 + nt + q2) ^ x7) << 4));
        mma16816(o[0][nt], a0, b);
        mma16816(o[1][nt], a1, b);
        mma16816(o[0][nt + 1], a0, b + 2);
        mma16816(o[1][nt + 1], a1, b + 2);
      }
    }
  }

  // ---- l reduction ----
  float* smL = (float*)(smem + SL);   // [2][128]
#pragma unroll
  for (int mt = 0; mt < 2; mt++)
#pragma unroll
    for (int h = 0; h < 2; h++) {
      float v = lp[mt][h];
      v += __shfl_xor_sync(0xffffffffu, v, 1);
      v += __shfl_xor_sync(0xffffffffu, v, 2);
      lp[mt][h] = v;
    }
  __syncthreads();
  if (c4 == 0) {
#pragma unroll
    for (int mt = 0; mt < 2; mt++)
#pragma unroll
      for (int h = 0; h < 2; h++)
        smL[wc * 128 + wr * 32 + mt * 16 + g + h * 8] = lp[mt][h];
  }
  __syncthreads();

#pragma unroll
  for (int mt = 0; mt < 2; mt++)
#pragma unroll
    for (int h = 0; h < 2; h++) {
      int rowl = wr * 32 + mt * 16 + g + h * 8;
      float lt = smL[rowl] + smL[128 + rowl];
      if (wc == 0 && c4 == 0) g_l[split][qbase + rowl] = lt;
#pragma unroll
      for (int nt = 0; nt < 8; nt++) {
        int col = wc * 64 + nt * 8 + c4 * 2;
        float2 ov = make_float2(o[mt][nt][h * 2], o[mt][nt][h * 2 + 1]);
        *(float2*)(&g_O[split][(size_t)(qbase + rowl) * DH + col]) = ov;
      }
    }
}

// ---------------- combine splits ----------------
__global__ __launch_bounds__(256) void combine_kernel(float* __restrict__ out) {
  int i = blockIdx.x * 256 + threadIdx.x;
  int row = i >> 7;
  float l = g_l[0][row] + g_l[1][row];
  out[i] = (g_O[0][i] + g_O[1][i]) / l;
}

// ---------------- launch ----------------
extern "C" void kernel_launch(void* const* d_in, const int* in_sizes, int n_in,
                              void* d_out, int out_size) {
  const float* x0 = nullptr;
  const void*  mask = nullptr;
  const float* wqkv = nullptr;
  for (int i = 0; i < n_in; i++) {
    long sz = in_sizes[i];
    if (sz == (long)NTOK * HCH)        x0   = (const float*)d_in[i];
    else if (sz == (long)NTOK * NTOK)  mask = d_in[i];
    else if (sz == (long)3 * DH * HCH) wqkv = (const float*)d_in[i];
  }

  // 1: mask dtype detect
  detect_kernel<<<1, 64>>>((const unsigned*)mask);

  // 2: fp32->fp16 (x and W)
  cvt_kernel<<<(NX4 + NW4) / 256, 256>>>(x0, wqkv);

  // 3: QKV GEMM + in-loop mask bit-packing
  cudaFuncSetAttribute(qkv_kernel, cudaFuncAttributeMaxDynamicSharedMemorySize, 73728);
  dim3 ggrid(NTOK / 64, 3);
  qkv_kernel<<<ggrid, 256, 73728>>>(mask);

  // 4: attention (profiled slot)
  cudaFuncSetAttribute(attn_kernel, cudaFuncAttributeMaxDynamicSharedMemorySize, A_SMEM);
  attn_kernel<<<NTOK / 128 * 2, 256, A_SMEM>>>();

  // 5: combine
  combine_kernel<<<NTOK * DH / 256, 256>>>((float*)d_out);
}

// round 17
// speedup vs baseline: 1.1087x; 1.1087x over previous
#include <cuda_runtime.h>
#include <cuda_fp16.h>
#include <cstdint>

#define NTOK 8192
#define HCH  2048
#define DH   128

// ---------------- device scratch ----------------
__device__ __align__(16) __half g_xh[NTOK * HCH];
__device__ __align__(16) __half g_wh[384 * HCH];
__device__ __align__(16) __half g_qh[NTOK * DH];   // scale folded
__device__ __align__(16) __half g_kh[NTOK * DH];
__device__ __align__(16) __half g_vh[NTOK * DH];
__device__ __align__(16) float  g_O[2][NTOK * DH]; // unnormalized per split
__device__ float g_l[2][NTOK];
__device__ __align__(16) uint32_t g_maskb[(size_t)NTOK * NTOK / 32];  // 8MB bitmask
__device__ int g_mask4;

// ---------------- helpers ----------------
__device__ __forceinline__ uint32_t smem_u32(const void* p) {
  uint32_t a;
  asm("{ .reg .u64 t; cvta.to.shared.u64 t, %1; cvt.u32.u64 %0, t; }" : "=r"(a) : "l"(p));
  return a;
}
__device__ __forceinline__ void ldm_x4(uint32_t* r, uint32_t a) {
  asm volatile("ldmatrix.sync.aligned.m8n8.x4.shared.b16 {%0,%1,%2,%3}, [%4];"
    : "=r"(r[0]), "=r"(r[1]), "=r"(r[2]), "=r"(r[3]) : "r"(a));
}
__device__ __forceinline__ void ldm_x4t(uint32_t* r, uint32_t a) {
  asm volatile("ldmatrix.sync.aligned.m8n8.x4.trans.shared.b16 {%0,%1,%2,%3}, [%4];"
    : "=r"(r[0]), "=r"(r[1]), "=r"(r[2]), "=r"(r[3]) : "r"(a));
}
__device__ __forceinline__ void stm_x4(uint32_t a, uint32_t r0, uint32_t r1,
                                       uint32_t r2, uint32_t r3) {
  asm volatile("stmatrix.sync.aligned.m8n8.x4.shared.b16 [%0], {%1,%2,%3,%4};"
    :: "r"(a), "r"(r0), "r"(r1), "r"(r2), "r"(r3) : "memory");
}
__device__ __forceinline__ void mma16816(float* d, const uint32_t* a, const uint32_t* b) {
  asm volatile("mma.sync.aligned.m16n8k16.row.col.f32.f16.f16.f32 "
    "{%0,%1,%2,%3}, {%4,%5,%6,%7}, {%8,%9}, {%0,%1,%2,%3};"
    : "+f"(d[0]), "+f"(d[1]), "+f"(d[2]), "+f"(d[3])
    : "r"(a[0]), "r"(a[1]), "r"(a[2]), "r"(a[3]), "r"(b[0]), "r"(b[1]));
}
__device__ __forceinline__ void cp16(uint32_t dst, const void* src) {
  asm volatile("cp.async.cg.shared.global [%0], [%1], 16;" :: "r"(dst), "l"(src) : "memory");
}
#define CP_COMMIT() asm volatile("cp.async.commit_group;" ::: "memory")
#define CP_WAIT0()  asm volatile("cp.async.wait_group 0;" ::: "memory")
#define CP_WAIT1()  asm volatile("cp.async.wait_group 1;" ::: "memory")
__device__ __forceinline__ __half2 hexp2_(__half2 x) {
  uint32_t r, a = *(uint32_t*)&x;
  asm("ex2.approx.f16x2 %0, %1;" : "=r"(r) : "r"(a));
  return *(__half2*)&r;
}
__device__ __forceinline__ uint32_t pack_h2(float x, float y) {
  __half2 h = __floats2half2_rn(x, y);
  return *(uint32_t*)&h;
}

// ---------------- mask dtype detect (1 block) ----------------
__global__ void detect_kernel(const unsigned* __restrict__ m) {
  __shared__ int s_ok;
  if (threadIdx.x == 0) s_ok = 1;
  __syncthreads();
  unsigned w = m[threadIdx.x];          // 64 threads, first 64 words
  if (w > 1u && w != 0x3f800000u) s_ok = 0;
  __syncthreads();
  if (threadIdx.x == 0) g_mask4 = s_ok;
}

// ---------------- mask -> bitmask via warp ballot ----------------
__global__ __launch_bounds__(256) void mask_bits_kernel(const void* __restrict__ mask) {
  const int w = (blockIdx.x * 256 + threadIdx.x) >> 5;
  const int lane = threadIdx.x & 31;
  if (g_mask4) {
    const unsigned* src = (const unsigned*)mask;
    for (int it = 0; it < 32; it++) {
      size_t wbase = (size_t)w * 128 + it * 4;
      size_t ebase = wbase * 32;
      uint32_t r0 = __ballot_sync(0xffffffffu, src[ebase + lane] != 0u);
      uint32_t r1 = __ballot_sync(0xffffffffu, src[ebase + 32 + lane] != 0u);
      uint32_t r2 = __ballot_sync(0xffffffffu, src[ebase + 64 + lane] != 0u);
      uint32_t r3 = __ballot_sync(0xffffffffu, src[ebase + 96 + lane] != 0u);
      if (lane == 0) *(uint4*)&g_maskb[wbase] = make_uint4(r0, r1, r2, r3);
    }
  } else {
    const uint8_t* src = (const uint8_t*)mask;
    for (int it = 0; it < 32; it++) {
      size_t wbase = (size_t)w * 128 + it * 4;
      size_t ebase = wbase * 32;
      uint32_t r0 = __ballot_sync(0xffffffffu, src[ebase + lane] != 0);
      uint32_t r1 = __ballot_sync(0xffffffffu, src[ebase + 32 + lane] != 0);
      uint32_t r2 = __ballot_sync(0xffffffffu, src[ebase + 64 + lane] != 0);
      uint32_t r3 = __ballot_sync(0xffffffffu, src[ebase + 96 + lane] != 0);
      if (lane == 0) *(uint4*)&g_maskb[wbase] = make_uint4(r0, r1, r2, r3);
    }
  }
}

// ---------------- fp32 -> fp16 (x and W fused) ----------------
#define NX4 (NTOK * HCH / 4)
#define NW4 (384 * HCH / 4)
__global__ __launch_bounds__(256) void cvt_kernel(const float* __restrict__ x,
                                                  const float* __restrict__ w) {
  int i = blockIdx.x * 256 + threadIdx.x;
  const float* src;
  __half* dst;
  int j;
  if (i < NX4) { src = x; dst = g_xh; j = i; }
  else         { src = w; dst = g_wh; j = i - NX4; }
  float4 v = ((const float4*)src)[j];
  uint2 o; o.x = pack_h2(v.x, v.y); o.y = pack_h2(v.z, v.w);
  ((uint2*)dst)[j] = o;
}

// ---------------- QKV GEMM (3-stage cp.async, BK=64) ----------
__global__ __launch_bounds__(256) void qkv_kernel() {
  extern __shared__ __align__(16) char smem[];
  const uint32_t sb = smem_u32(smem);
  const int tid = threadIdx.x, lane = tid & 31, wid = tid >> 5;
  const int wr = wid & 3, wc = wid >> 2;
  const int g = lane >> 2, c4 = lane & 3;
  const int m0 = blockIdx.x * 64;
  const int which = blockIdx.y;
  const __half* wsrc = g_wh + (size_t)which * 128 * HCH;

  float acc[8][4];
#pragma unroll
  for (int nt = 0; nt < 8; nt++)
#pragma unroll
    for (int r = 0; r < 4; r++) acc[nt][r] = 0.f;

  const int x7 = lane & 7, hiA = lane >> 4, hiB = (lane >> 3) & 1, q2 = (lane >> 4) & 1;
  const int l15 = lane & 15;

  auto issue = [&](int kc) {
    int st = kc % 3;
    uint32_t bufA = sb + (uint32_t)st * 8192;
    uint32_t bufB = sb + 24576 + (uint32_t)st * 16384;
#pragma unroll
    for (int i = 0; i < 2; i++) {
      int idx = tid + i * 256;
      int r = idx >> 3, ch = idx & 7;
      uint32_t sw = (uint32_t)r * 128 + (uint32_t)((ch ^ (r & 7)) << 4);
      cp16(bufA + sw, g_xh + (size_t)(m0 + r) * HCH + kc * 64 + ch * 8);
    }
#pragma unroll
    for (int i = 0; i < 4; i++) {
      int idx = tid + i * 256;
      int r = idx >> 3, ch = idx & 7;
      uint32_t sw = (uint32_t)r * 128 + (uint32_t)((ch ^ (r & 7)) << 4);
      cp16(bufB + sw, wsrc + (size_t)r * HCH + kc * 64 + ch * 8);
    }
    CP_COMMIT();
  };

  issue(0);
  issue(1);
  for (int kc = 0; kc < 32; kc++) {
    if (kc < 31) { CP_WAIT1(); } else { CP_WAIT0(); }
    __syncthreads();
    if (kc < 30) issue(kc + 2);
    int st = kc % 3;
    const uint32_t bufA = sb + (uint32_t)st * 8192;
    const uint32_t bufB = sb + 24576 + (uint32_t)st * 16384;
    const uint32_t aBase = bufA + (uint32_t)(wr * 16 + l15) * 128;
    const uint32_t bBase = bufB + (uint32_t)(wc * 64 + x7) * 128;
#pragma unroll
    for (int ks = 0; ks < 4; ks++) {
      uint32_t a0[4];
      ldm_x4(a0, aBase + (((ks * 2 + hiA) ^ x7) << 4));
#pragma unroll
      for (int nt = 0; nt < 8; nt += 2) {
        uint32_t b[4];
        ldm_x4(b, bBase + (uint32_t)(nt + q2) * 8 * 128 + (((ks * 2 + hiB) ^ x7) << 4));
        mma16816(acc[nt], a0, b);
        mma16816(acc[nt + 1], a0, b + 2);
      }
    }
  }

  const float sc = (which == 0) ? (1.4426950408889634f / 128.0f) : 1.0f;
  __half* dst = (which == 0) ? g_qh : (which == 1) ? g_kh : g_vh;
#pragma unroll
  for (int h = 0; h < 2; h++) {
    int row = m0 + wr * 16 + g + h * 8;
#pragma unroll
    for (int nt = 0; nt < 8; nt++) {
      int col = wc * 64 + nt * 8 + c4 * 2;
      *(uint32_t*)(dst + (size_t)row * DH + col) =
          pack_h2(acc[nt][h * 2] * sc, acc[nt][h * 2 + 1] * sc);
    }
  }
}

// ---------------- attention (R15 verbatim — bitmask path) ----------------
#define SK 0
#define SV 65536
#define SP 131072
#define SM2 163840
#define SL (SM2 + 4096)
#define A_SMEM (SL + 1024)

__global__ __launch_bounds__(256, 1) void attn_kernel() {
  extern __shared__ __align__(16) char smem[];
  const uint32_t sb = smem_u32(smem);
  const int tid = threadIdx.x, lane = tid & 31, wid = tid >> 5;
  const int wr = wid & 3, wc = wid >> 2;
  const int g = lane >> 2, c4 = lane & 3;
  const int qt = blockIdx.x >> 1;
  const int qbase = qt * 128;
  const int split = blockIdx.x & 1;
  const int barid = wr + 1;

  const int x7 = lane & 7, hiA = lane >> 4, hiB = (lane >> 3) & 1, q2 = (lane >> 4) & 1;
  const int l15 = lane & 15;
  const int c42 = c4 * 2;

  auto issue = [&](int kb) {
    const int kcol = split * 4096 + kb * 128;
    const uint32_t kB = sb + SK + (uint32_t)(kb & 1) * 32768;
    const uint32_t vB = sb + SV + (uint32_t)(kb & 1) * 32768;
    const uint32_t mB = sb + SM2 + (uint32_t)(kb & 1) * 2048;
#pragma unroll
    for (int i = 0; i < 8; i++) {
      int idx = tid + i * 256;
      int r = idx >> 4, ch = idx & 15;
      uint32_t sw = (uint32_t)r * 256 + (uint32_t)((ch ^ (r & 7)) << 4);
      cp16(kB + sw, g_kh + (size_t)(kcol + r) * DH + ch * 8);
      cp16(vB + sw, g_vh + (size_t)(kcol + r) * DH + ch * 8);
    }
    if (tid < 128) {   // mask bits: 16B per row
      cp16(mB + (uint32_t)tid * 16,
           (const uint8_t*)g_maskb + (size_t)(qbase + tid) * 1024 + split * 512 + kb * 16);
    }
    CP_COMMIT();
  };

  issue(0);

  // stage Q into the P region, extract fragments into registers
#pragma unroll
  for (int i = 0; i < 8; i++) {
    int idx = tid + i * 256;
    int r = idx >> 4, ch = idx & 15;
    uint4 v = *(const uint4*)(g_qh + (size_t)(qbase + r) * DH + ch * 8);
    *(uint4*)(smem + SP + r * 256 + ((ch ^ (r & 7)) << 4)) = v;
  }
  __syncthreads();
  uint32_t qa[8][2][4];
  {
    const uint32_t qB = sb + SP + (uint32_t)(wr * 32 + l15) * 256;
#pragma unroll
    for (int ks = 0; ks < 8; ks++) {
      ldm_x4(qa[ks][0], qB + (((ks * 2 + hiA) ^ x7) << 4));
      ldm_x4(qa[ks][1], qB + 16 * 256 + (((ks * 2 + hiA) ^ x7) << 4));
    }
  }
  __syncthreads();   // everyone has Q frags before P overwrites begin

  float o[2][8][4];
#pragma unroll
  for (int mt = 0; mt < 2; mt++)
#pragma unroll
    for (int nt = 0; nt < 8; nt++)
#pragma unroll
      for (int r = 0; r < 4; r++) o[mt][nt][r] = 0.f;
  float lp[2][2] = {{0.f, 0.f}, {0.f, 0.f}};

  const int t8 = lane >> 3;            // stmatrix tile index
  const int hh = t8 & 1, ntp = t8 >> 1, r8 = lane & 7;

  for (int kb = 0; kb < 32; kb++) {
    CP_WAIT0();
    __syncthreads();
    if (kb < 31) issue(kb + 1);

    const uint32_t kB = sb + SK + (uint32_t)(kb & 1) * 32768 + (uint32_t)(wc * 64 + x7) * 256;
    const uint32_t vB = sb + SV + (uint32_t)(kb & 1) * 32768 + (uint32_t)l15 * 256;
    const uint32_t mB = sb + SM2 + (uint32_t)(kb & 1) * 2048 + (uint32_t)(wc * 8);

    // ---- S = Q @ K^T ----
    float s[2][8][4];
#pragma unroll
    for (int mt = 0; mt < 2; mt++)
#pragma unroll
      for (int nt = 0; nt < 8; nt++)
#pragma unroll
        for (int r = 0; r < 4; r++) s[mt][nt][r] = 0.f;
#pragma unroll
    for (int ks = 0; ks < 8; ks++) {
#pragma unroll
      for (int nt = 0; nt < 8; nt += 2) {
        uint32_t b[4];
        ldm_x4(b, kB + (uint32_t)(nt + q2) * 8 * 256 + (((ks * 2 + hiB) ^ x7) << 4));
        mma16816(s[0][nt], qa[ks][0], b);
        mma16816(s[1][nt], qa[ks][1], b);
        mma16816(s[0][nt + 1], qa[ks][0], b + 2);
        mma16816(s[1][nt + 1], qa[ks][1], b + 2);
      }
    }

    // ---- fp16x2 softmax (multiplier from mask bits), stmatrix P ----
    asm volatile("bar.sync %0, 64;" :: "r"(barid) : "memory");
#pragma unroll
    for (int mt = 0; mt < 2; mt++) {
      uint32_t pk[2][8];
#pragma unroll
      for (int h = 0; h < 2; h++) {
        int rowl = wr * 32 + mt * 16 + h * 8 + g;
        uint64_t mb;
        asm volatile("ld.shared.b64 %0, [%1];" : "=l"(mb) : "r"(mB + (uint32_t)rowl * 16));
        uint32_t mlo = (uint32_t)mb, mhi = (uint32_t)(mb >> 32);
        __half2 hs = __halves2half2(__float2half(0.f), __float2half(0.f));
#pragma unroll
        for (int nt = 0; nt < 8; nt++) {
          uint32_t b2 = ((nt < 4) ? (mlo >> (nt * 8 + c42)) : (mhi >> ((nt - 4) * 8 + c42))) & 3u;
          uint32_t m2u = 0x3C003C00u - (b2 & 1u) * 0x3C00u - (b2 >> 1) * 0x3C000000u;
          __half2 m2 = *(__half2*)&m2u;
          __half2 sh = __floats2half2_rn(s[mt][nt][h * 2], s[mt][nt][h * 2 + 1]);
          __half2 p = __hmul2(hexp2_(sh), m2);
          pk[h][nt] = *(uint32_t*)&p;
          hs = __hadd2(hs, p);
        }
        float2 f = __half22float2(hs);
        lp[mt][h] += f.x + f.y;
      }
      int srow = wr * 32 + mt * 16 + hh * 8 + r8;
      uint32_t sbase = sb + SP + (uint32_t)srow * 256;
      int sr7 = srow & 7;
#pragma unroll
      for (int j = 0; j < 4; j++) {
        int ntj = 2 * j + ntp;
        uint32_t addr = sbase + (uint32_t)(((wc * 8 + ntj) ^ sr7) << 4);
        stm_x4(addr, pk[0][2 * j], pk[1][2 * j], pk[0][2 * j + 1], pk[1][2 * j + 1]);
      }
    }
    asm volatile("bar.sync %0, 64;" :: "r"(barid) : "memory");

    // ---- O += P @ V ----
    const uint32_t pB = sb + SP + (uint32_t)(wr * 32 + l15) * 256;
#pragma unroll
    for (int ks = 0; ks < 8; ks++) {
      uint32_t a0[4], a1[4];
      ldm_x4(a0, pB + (((ks * 2 + hiA) ^ x7) << 4));
      ldm_x4(a1, pB + 16 * 256 + (((ks * 2 + hiA) ^ x7) << 4));
      uint32_t vrow = vB + (uint32_t)(ks * 16) * 256;
#pragma unroll
      for (int nt = 0; nt < 8; nt += 2) {
        uint32_t b[4];
        ldm_x4t(b, vrow + (uint32_t)(((wc * 8 + nt + q2) ^ x7) << 4));
        mma16816(o[0][nt], a0, b);
        mma16816(o[1][nt], a1, b);
        mma16816(o[0][nt + 1], a0, b + 2);
        mma16816(o[1][nt + 1], a1, b + 2);
      }
    }
  }

  // ---- l reduction ----
  float* smL = (float*)(smem + SL);   // [2][128]
#pragma unroll
  for (int mt = 0; mt < 2; mt++)
#pragma unroll
    for (int h = 0; h < 2; h++) {
      float v = lp[mt][h];
      v += __shfl_xor_sync(0xffffffffu, v, 1);
      v += __shfl_xor_sync(0xffffffffu, v, 2);
      lp[mt][h] = v;
    }
  __syncthreads();
  if (c4 == 0) {
#pragma unroll
    for (int mt = 0; mt < 2; mt++)
#pragma unroll
      for (int h = 0; h < 2; h++)
        smL[wc * 128 + wr * 32 + mt * 16 + g + h * 8] = lp[mt][h];
  }
  __syncthreads();

#pragma unroll
  for (int mt = 0; mt < 2; mt++)
#pragma unroll
    for (int h = 0; h < 2; h++) {
      int rowl = wr * 32 + mt * 16 + g + h * 8;
      float lt = smL[rowl] + smL[128 + rowl];
      if (wc == 0 && c4 == 0) g_l[split][qbase + rowl] = lt;
#pragma unroll
      for (int nt = 0; nt < 8; nt++) {
        int col = wc * 64 + nt * 8 + c4 * 2;
        float2 ov = make_float2(o[mt][nt][h * 2], o[mt][nt][h * 2 + 1]);
        *(float2*)(&g_O[split][(size_t)(qbase + rowl) * DH + col]) = ov;
      }
    }
}

// ---------------- combine splits ----------------
__global__ __launch_bounds__(256) void combine_kernel(float* __restrict__ out) {
  int i = blockIdx.x * 256 + threadIdx.x;
  int row = i >> 7;
  float l = g_l[0][row] + g_l[1][row];
  out[i] = (g_O[0][i] + g_O[1][i]) / l;
}

// ---------------- launch (forked capture branch for the mask pass) ----------
extern "C" void kernel_launch(void* const* d_in, const int* in_sizes, int n_in,
                              void* d_out, int out_size) {
  const float* x0 = nullptr;
  const void*  mask = nullptr;
  const float* wqkv = nullptr;
  for (int i = 0; i < n_in; i++) {
    long sz = in_sizes[i];
    if (sz == (long)NTOK * HCH)        x0   = (const float*)d_in[i];
    else if (sz == (long)NTOK * NTOK)  mask = d_in[i];
    else if (sz == (long)3 * DH * HCH) wqkv = (const float*)d_in[i];
  }

  static cudaStream_t s2 = nullptr;
  static cudaEvent_t e1 = nullptr, e2 = nullptr;
  static int init_ok = -1;
  if (init_ok < 0) {
    init_ok = 1;
    if (cudaStreamCreateWithFlags(&s2, cudaStreamNonBlocking) != cudaSuccess) init_ok = 0;
    if (init_ok && cudaEventCreateWithFlags(&e1, cudaEventDisableTiming) != cudaSuccess) init_ok = 0;
    if (init_ok && cudaEventCreateWithFlags(&e2, cudaEventDisableTiming) != cudaSuccess) init_ok = 0;
  }

  cudaFuncSetAttribute(qkv_kernel, cudaFuncAttributeMaxDynamicSharedMemorySize, 73728);
  cudaFuncSetAttribute(attn_kernel, cudaFuncAttributeMaxDynamicSharedMemorySize, A_SMEM);

  detect_kernel<<<1, 64>>>((const unsigned*)mask);

  if (init_ok) {
    // fork: mask_bits runs concurrently with cvt + qkv
    cudaEventRecord(e1, 0);
    cudaStreamWaitEvent(s2, e1, 0);
    mask_bits_kernel<<<2048, 256, 0, s2>>>(mask);
    cudaEventRecord(e2, s2);

    cvt_kernel<<<(NX4 + NW4) / 256, 256>>>(x0, wqkv);
    dim3 ggrid(NTOK / 64, 3);
    qkv_kernel<<<ggrid, 256, 73728>>>();

    cudaStreamWaitEvent(0, e2, 0);   // join before attention
  } else {
    // fallback: serial
    mask_bits_kernel<<<2048, 256>>>(mask);
    cvt_kernel<<<(NX4 + NW4) / 256, 256>>>(x0, wqkv);
    dim3 ggrid(NTOK / 64, 3);
    qkv_kernel<<<ggrid, 256, 73728>>>();
  }

  attn_kernel<<<NTOK / 128 * 2, 256, A_SMEM>>>();
  combine_kernel<<<NTOK * DH / 256, 256>>>((float*)d_out);
}